// round 3
// baseline (speedup 1.0000x reference)
#include <cuda_runtime.h>

// Scratch for intermediate h3[256] and completion ticket. __device__ globals: no allocation.
__device__ float g_h3[256];
__device__ unsigned int g_cnt = 0;

// Fused: 256 blocks x 128 threads, single wave (8 blocks/SM allowed, 148 SMs -> all resident).
// Each block redundantly builds h[2048] in shared (~7K FLOPs, free), computes one
// row of the 256x2048 GEMV, publishes g_h3[row], takes a ticket; the LAST block
// to arrive runs the 6x256 epilogue immediately (no spin-wait) and resets the ticket.
__global__ void __launch_bounds__(128, 8) actor_fused(
    const float* __restrict__ x,
    const float* __restrict__ conv_w, const float* __restrict__ conv_b,
    const float* __restrict__ w0, const float* __restrict__ b0,
    const float* __restrict__ w1, const float* __restrict__ b1,
    const float* __restrict__ w2, const float* __restrict__ b2,
    const float* __restrict__ w3, const float* __restrict__ b3,
    const float* __restrict__ w4, const float* __restrict__ b4,
    float* __restrict__ out)
{
    __shared__ __align__(16) float h[2048];
    __shared__ float red[4];
    __shared__ int s_last;

    const int c = threadIdx.x;           // 0..127
    const int row = blockIdx.x;

    // ---- issue ALL global loads up front: one exposed DRAM latency ----
    const float4* __restrict__ w3r = reinterpret_cast<const float4*>(w3 + (size_t)row * 2048);
    float4 wv0 = w3r[c];
    float4 wv1 = w3r[c + 128];
    float4 wv2 = w3r[c + 256];
    float4 wv3 = w3r[c + 384];

    // epilogue operands, prefetched in every block (any block might be last)
    float w4a[6], w4b[6];
#pragma unroll
    for (int j = 0; j < 6; j++) {
        w4a[j] = w4[j * 256 + c];
        w4b[j] = w4[j * 256 + c + 128];
    }
    const float b4v = (c < 6) ? b4[c] : 0.0f;
    const float b3v = b3[row];

    const float x07 = x[7];
    const float x17 = x[15];
    const float x47 = x[39];

    float x2r[8], x3r[8], x4r[6];
#pragma unroll
    for (int i = 0; i < 8; i++) { x2r[i] = x[16 + i]; x3r[i] = x[24 + i]; }
#pragma unroll
    for (int i = 0; i < 6; i++) { x4r[i] = x[32 + i]; }

    float cw[4];
#pragma unroll
    for (int k = 0; k < 4; k++) cw[k] = conv_w[c * 4 + k];
    const float cb = conv_b[c];
    const float w0v = w0[c], b0v = b0[c];
    const float w1v = w1[c], b1v = b1[c];
    const float w2v = w2[c], b2v = b2[c];

    // ---- build h (thread c owns channel c across all segments) ----
    h[c]       = fmaxf(fmaf(w0v, x07, b0v), 0.0f);                 // s0: [0,128)
    h[128 + c] = fmaxf(fmaf(w1v, x17, b1v), 0.0f);                 // s1: [128,256)

#pragma unroll
    for (int t = 0; t < 5; t++) {                                   // s2,s3: conv T=5
        float a2 = cb, a3 = cb;
#pragma unroll
        for (int k = 0; k < 4; k++) {
            a2 = fmaf(cw[k], x2r[t + k], a2);
            a3 = fmaf(cw[k], x3r[t + k], a3);
        }
        h[256 + c * 5 + t] = fmaxf(a2, 0.0f);                       // [256,896)
        h[896 + c * 5 + t] = fmaxf(a3, 0.0f);                       // [896,1536)
    }
#pragma unroll
    for (int t = 0; t < 3; t++) {                                   // s4: conv over x[4,:6], T=3
        float a4 = cb;
#pragma unroll
        for (int k = 0; k < 4; k++) a4 = fmaf(cw[k], x4r[t + k], a4);
        h[1536 + c * 3 + t] = fmaxf(a4, 0.0f);                      // [1536,1920)
    }
    h[1920 + c] = fmaf(w2v, x47, b2v);                              // s5: NO relu, [1920,2048)

    __syncthreads();

    // ---- row dot: w3[row, :] . h ----
    const float4* __restrict__ h4 = reinterpret_cast<const float4*>(h);
    float4 hv0 = h4[c];
    float4 hv1 = h4[c + 128];
    float4 hv2 = h4[c + 256];
    float4 hv3 = h4[c + 384];

    float acc = 0.0f;
    acc = fmaf(wv0.x, hv0.x, acc); acc = fmaf(wv0.y, hv0.y, acc);
    acc = fmaf(wv0.z, hv0.z, acc); acc = fmaf(wv0.w, hv0.w, acc);
    acc = fmaf(wv1.x, hv1.x, acc); acc = fmaf(wv1.y, hv1.y, acc);
    acc = fmaf(wv1.z, hv1.z, acc); acc = fmaf(wv1.w, hv1.w, acc);
    acc = fmaf(wv2.x, hv2.x, acc); acc = fmaf(wv2.y, hv2.y, acc);
    acc = fmaf(wv2.z, hv2.z, acc); acc = fmaf(wv2.w, hv2.w, acc);
    acc = fmaf(wv3.x, hv3.x, acc); acc = fmaf(wv3.y, hv3.y, acc);
    acc = fmaf(wv3.z, hv3.z, acc); acc = fmaf(wv3.w, hv3.w, acc);

#pragma unroll
    for (int o = 16; o > 0; o >>= 1) acc += __shfl_xor_sync(0xffffffffu, acc, o);
    if ((c & 31) == 0) red[c >> 5] = acc;
    __syncthreads();

    if (c == 0) {
        float s = red[0] + red[1] + red[2] + red[3] + b3v;
        g_h3[row] = fmaxf(s, 0.0f);
        __threadfence();                              // publish g_h3[row]
        unsigned int t = atomicAdd(&g_cnt, 1u);       // take ticket
        s_last = (t == 255u);
    }
    __syncthreads();

    if (!s_last) return;

    // ---- LAST block: epilogue out = w4 @ relu-h3 + b4 ----
    __threadfence();                                  // acquire g_h3 from other SMs
    const float hr0 = g_h3[c];
    const float hr1 = g_h3[c + 128];

    float a[6];
#pragma unroll
    for (int j = 0; j < 6; j++) {
        a[j] = fmaf(w4a[j], hr0, w4b[j] * hr1);
    }
#pragma unroll
    for (int o = 16; o > 0; o >>= 1) {
#pragma unroll
        for (int j = 0; j < 6; j++) a[j] += __shfl_xor_sync(0xffffffffu, a[j], o);
    }

    __shared__ float red2[4][6];
    if ((c & 31) == 0) {
#pragma unroll
        for (int j = 0; j < 6; j++) red2[c >> 5][j] = a[j];
    }
    __syncthreads();
    if (c < 6) {
        out[c] = red2[0][c] + red2[1][c] + red2[2][c] + red2[3][c] + b4v;
    }
    if (c == 6) {
        g_cnt = 0;   // reset for next graph replay (deterministic)
    }
}

extern "C" void kernel_launch(void* const* d_in, const int* in_sizes, int n_in,
                              void* d_out, int out_size)
{
    const float* x      = (const float*)d_in[0];
    const float* conv_w = (const float*)d_in[1];
    const float* conv_b = (const float*)d_in[2];
    const float* w0     = (const float*)d_in[3];
    const float* b0     = (const float*)d_in[4];
    const float* w1     = (const float*)d_in[5];
    const float* b1     = (const float*)d_in[6];
    const float* w2     = (const float*)d_in[7];
    const float* b2     = (const float*)d_in[8];
    const float* w3     = (const float*)d_in[9];
    const float* b3     = (const float*)d_in[10];
    const float* w4     = (const float*)d_in[11];
    const float* b4     = (const float*)d_in[12];
    float* out = (float*)d_out;

    actor_fused<<<256, 128>>>(x, conv_w, conv_b, w0, b0, w1, b1, w2, b2,
                              w3, b3, w4, b4, out);
}

// round 4
// speedup vs baseline: 1.0350x; 1.0350x over previous
#include <cuda_runtime.h>

// Scratch + ticket. __device__ globals: no allocation.
__device__ float g_h3[256];
__device__ unsigned int g_cnt = 0;

__device__ __forceinline__ float ldcg(const float* p) {
    float v;
    asm volatile("ld.global.cg.f32 %0, [%1];" : "=f"(v) : "l"(p));
    return v;
}
__device__ __forceinline__ void stcg(float* p, float v) {
    asm volatile("st.global.cg.f32 [%0], %1;" :: "l"(p), "f"(v) : "memory");
}

// 64 blocks x 128 threads. Each block: builds h[2048] in shared (redundant, cheap),
// then each WARP computes one full row dot (64 elems/thread, MLP=16, warp-shuffle
// reduce only -- no cross-warp reduction). 64 ticket atomics instead of 256.
// Last-arriving block runs the 6x256 epilogue.
__global__ void __launch_bounds__(128) actor_fused(
    const float* __restrict__ x,
    const float* __restrict__ conv_w, const float* __restrict__ conv_b,
    const float* __restrict__ w0, const float* __restrict__ b0,
    const float* __restrict__ w1, const float* __restrict__ b1,
    const float* __restrict__ w2, const float* __restrict__ b2,
    const float* __restrict__ w3, const float* __restrict__ b3,
    const float* __restrict__ w4, const float* __restrict__ b4,
    float* __restrict__ out)
{
    __shared__ __align__(16) float h[2048];
    __shared__ int s_last;

    const int c    = threadIdx.x;        // 0..127
    const int wid  = c >> 5;             // 0..3
    const int lane = c & 31;
    const int row  = (blockIdx.x << 2) + wid;   // this warp's GEMV row

    // ---- epilogue operands prefetched (any block may be last) ----
    float w4a[6], w4b[6];
#pragma unroll
    for (int j = 0; j < 6; j++) {
        w4a[j] = w4[j * 256 + c];
        w4b[j] = w4[j * 256 + c + 128];
    }
    const float b4v = (c < 6) ? b4[c] : 0.0f;
    const float b3v = b3[row];

    // ---- inputs for h build ----
    const float x07 = x[7];
    const float x17 = x[15];
    const float x47 = x[39];
    float x2r[8], x3r[8], x4r[6];
#pragma unroll
    for (int i = 0; i < 8; i++) { x2r[i] = x[16 + i]; x3r[i] = x[24 + i]; }
#pragma unroll
    for (int i = 0; i < 6; i++) { x4r[i] = x[32 + i]; }

    float cw[4];
#pragma unroll
    for (int k = 0; k < 4; k++) cw[k] = conv_w[c * 4 + k];
    const float cb = conv_b[c];
    const float w0v = w0[c], b0v = b0[c];
    const float w1v = w1[c], b1v = b1[c];
    const float w2v = w2[c], b2v = b2[c];

    // ---- build h (thread c owns channel c) ----
    h[c]       = fmaxf(fmaf(w0v, x07, b0v), 0.0f);                 // s0 [0,128)
    h[128 + c] = fmaxf(fmaf(w1v, x17, b1v), 0.0f);                 // s1 [128,256)
#pragma unroll
    for (int t = 0; t < 5; t++) {                                   // s2,s3 conv T=5
        float a2 = cb, a3 = cb;
#pragma unroll
        for (int k = 0; k < 4; k++) {
            a2 = fmaf(cw[k], x2r[t + k], a2);
            a3 = fmaf(cw[k], x3r[t + k], a3);
        }
        h[256 + c * 5 + t] = fmaxf(a2, 0.0f);
        h[896 + c * 5 + t] = fmaxf(a3, 0.0f);
    }
#pragma unroll
    for (int t = 0; t < 3; t++) {                                   // s4 conv T=3
        float a4 = cb;
#pragma unroll
        for (int k = 0; k < 4; k++) a4 = fmaf(cw[k], x4r[t + k], a4);
        h[1536 + c * 3 + t] = fmaxf(a4, 0.0f);
    }
    h[1920 + c] = fmaf(w2v, x47, b2v);                              // s5 (no relu)

    __syncthreads();

    // ---- warp-per-row dot: w3[row,:] . h, 64 elems/thread ----
    const float4* __restrict__ w3r = reinterpret_cast<const float4*>(w3 + (size_t)row * 2048);
    const float4* __restrict__ h4  = reinterpret_cast<const float4*>(h);

    float acc0 = 0.0f, acc1 = 0.0f;
#pragma unroll
    for (int i = 0; i < 16; i += 2) {
        float4 wv0 = w3r[lane + 32 * i];
        float4 wv1 = w3r[lane + 32 * (i + 1)];
        float4 hv0 = h4[lane + 32 * i];
        float4 hv1 = h4[lane + 32 * (i + 1)];
        acc0 = fmaf(wv0.x, hv0.x, acc0); acc0 = fmaf(wv0.y, hv0.y, acc0);
        acc0 = fmaf(wv0.z, hv0.z, acc0); acc0 = fmaf(wv0.w, hv0.w, acc0);
        acc1 = fmaf(wv1.x, hv1.x, acc1); acc1 = fmaf(wv1.y, hv1.y, acc1);
        acc1 = fmaf(wv1.z, hv1.z, acc1); acc1 = fmaf(wv1.w, hv1.w, acc1);
    }
    float acc = acc0 + acc1;
#pragma unroll
    for (int o = 16; o > 0; o >>= 1) acc += __shfl_xor_sync(0xffffffffu, acc, o);
    if (lane == 0) {
        stcg(&g_h3[row], fmaxf(acc + b3v, 0.0f));
    }

    __syncthreads();
    if (c == 0) {
        __threadfence();                              // publish g_h3 rows
        unsigned int t = atomicAdd(&g_cnt, 1u);       // take ticket (64 total)
        s_last = (t == 63u);
    }
    __syncthreads();
    if (!s_last) return;

    // ---- LAST block: out = w4 @ relu-h3 + b4 ----
    __threadfence();
    const float hr0 = ldcg(&g_h3[c]);
    const float hr1 = ldcg(&g_h3[c + 128]);

    float a[6];
#pragma unroll
    for (int j = 0; j < 6; j++) a[j] = fmaf(w4a[j], hr0, w4b[j] * hr1);
#pragma unroll
    for (int o = 16; o > 0; o >>= 1) {
#pragma unroll
        for (int j = 0; j < 6; j++) a[j] += __shfl_xor_sync(0xffffffffu, a[j], o);
    }

    __shared__ float red2[4][6];
    if (lane == 0) {
#pragma unroll
        for (int j = 0; j < 6; j++) red2[wid][j] = a[j];
    }
    __syncthreads();
    if (c < 6) out[c] = red2[0][c] + red2[1][c] + red2[2][c] + red2[3][c] + b4v;
    if (c == 6) g_cnt = 0;   // reset for next replay
}

extern "C" void kernel_launch(void* const* d_in, const int* in_sizes, int n_in,
                              void* d_out, int out_size)
{
    const float* x      = (const float*)d_in[0];
    const float* conv_w = (const float*)d_in[1];
    const float* conv_b = (const float*)d_in[2];
    const float* w0     = (const float*)d_in[3];
    const float* b0     = (const float*)d_in[4];
    const float* w1     = (const float*)d_in[5];
    const float* b1     = (const float*)d_in[6];
    const float* w2     = (const float*)d_in[7];
    const float* b2     = (const float*)d_in[8];
    const float* w3     = (const float*)d_in[9];
    const float* b3     = (const float*)d_in[10];
    const float* w4     = (const float*)d_in[11];
    const float* b4     = (const float*)d_in[12];
    float* out = (float*)d_out;

    actor_fused<<<64, 128>>>(x, conv_w, conv_b, w0, b0, w1, b1, w2, b2,
                             w3, b3, w4, b4, out);
}

// round 5
// speedup vs baseline: 1.1928x; 1.1525x over previous
#include <cuda_runtime.h>

// K0: out[j] = b4[j]  (runs before K1 in stream order; gives REDG a clean base)
__global__ void actor_init(const float* __restrict__ b4, float* __restrict__ out)
{
    if (threadIdx.x < 6) out[threadIdx.x] = b4[threadIdx.x];
}

// K1: 64 blocks x 128 threads. Each block builds h[2048] in shared (redundant,
// ~7K FLOPs). Each WARP computes one row of the 256x2048 GEMV (w3 row prefetched
// into registers at entry, overlapping the h build), then folds its row straight
// into out[0..5] via fire-and-forget red.global.add.f32. No global barrier,
// no ticket, no epilogue rendezvous.
__global__ void __launch_bounds__(128) actor_main(
    const float* __restrict__ x,
    const float* __restrict__ conv_w, const float* __restrict__ conv_b,
    const float* __restrict__ w0, const float* __restrict__ b0,
    const float* __restrict__ w1, const float* __restrict__ b1,
    const float* __restrict__ w2, const float* __restrict__ b2,
    const float* __restrict__ w3, const float* __restrict__ b3,
    const float* __restrict__ w4,
    float* __restrict__ out)
{
    __shared__ __align__(16) float h[2048];

    const int c    = threadIdx.x;        // 0..127
    const int wid  = c >> 5;             // 0..3
    const int lane = c & 31;
    const int row  = (blockIdx.x << 2) + wid;   // this warp's GEMV row

    // ---- prefetch: full w3 row into regs (16 x LDG.128, MLP=16) ----
    const float4* __restrict__ w3r = reinterpret_cast<const float4*>(w3 + (size_t)row * 2048);
    float4 wv[16];
#pragma unroll
    for (int i = 0; i < 16; i++) wv[i] = w3r[lane + 32 * i];

    // epilogue column + bias for this row
    const float w4c = (lane < 6) ? w4[lane * 256 + row] : 0.0f;
    const float b3v = b3[row];

    // ---- inputs for h build ----
    const float x07 = x[7];
    const float x17 = x[15];
    const float x47 = x[39];
    float x2r[8], x3r[8], x4r[6];
#pragma unroll
    for (int i = 0; i < 8; i++) { x2r[i] = x[16 + i]; x3r[i] = x[24 + i]; }
#pragma unroll
    for (int i = 0; i < 6; i++) { x4r[i] = x[32 + i]; }

    float cw[4];
#pragma unroll
    for (int k = 0; k < 4; k++) cw[k] = conv_w[c * 4 + k];
    const float cb = conv_b[c];
    const float w0v = w0[c], b0v = b0[c];
    const float w1v = w1[c], b1v = b1[c];
    const float w2v = w2[c], b2v = b2[c];

    // ---- build h (thread c owns channel c) ----
    h[c]       = fmaxf(fmaf(w0v, x07, b0v), 0.0f);                 // s0 [0,128)
    h[128 + c] = fmaxf(fmaf(w1v, x17, b1v), 0.0f);                 // s1 [128,256)
#pragma unroll
    for (int t = 0; t < 5; t++) {                                   // s2,s3 conv T=5
        float a2 = cb, a3 = cb;
#pragma unroll
        for (int k = 0; k < 4; k++) {
            a2 = fmaf(cw[k], x2r[t + k], a2);
            a3 = fmaf(cw[k], x3r[t + k], a3);
        }
        h[256 + c * 5 + t] = fmaxf(a2, 0.0f);
        h[896 + c * 5 + t] = fmaxf(a3, 0.0f);
    }
#pragma unroll
    for (int t = 0; t < 3; t++) {                                   // s4 conv T=3
        float a4 = cb;
#pragma unroll
        for (int k = 0; k < 4; k++) a4 = fmaf(cw[k], x4r[t + k], a4);
        h[1536 + c * 3 + t] = fmaxf(a4, 0.0f);
    }
    h[1920 + c] = fmaf(w2v, x47, b2v);                              // s5 (no relu)

    __syncthreads();

    // ---- row dot: registers (w3) x shared (h), 64 elems/thread ----
    const float4* __restrict__ h4 = reinterpret_cast<const float4*>(h);
    float acc0 = 0.0f, acc1 = 0.0f;
#pragma unroll
    for (int i = 0; i < 16; i += 2) {
        float4 hv0 = h4[lane + 32 * i];
        float4 hv1 = h4[lane + 32 * (i + 1)];
        acc0 = fmaf(wv[i].x,     hv0.x, acc0); acc0 = fmaf(wv[i].y,     hv0.y, acc0);
        acc0 = fmaf(wv[i].z,     hv0.z, acc0); acc0 = fmaf(wv[i].w,     hv0.w, acc0);
        acc1 = fmaf(wv[i + 1].x, hv1.x, acc1); acc1 = fmaf(wv[i + 1].y, hv1.y, acc1);
        acc1 = fmaf(wv[i + 1].z, hv1.z, acc1); acc1 = fmaf(wv[i + 1].w, hv1.w, acc1);
    }
    float acc = acc0 + acc1;
#pragma unroll
    for (int o = 16; o > 0; o >>= 1) acc += __shfl_xor_sync(0xffffffffu, acc, o);
    // butterfly -> every lane holds the full row sum

    const float h3r = fmaxf(acc + b3v, 0.0f);

    // lanes 0..5: fold this row into out[j], fire-and-forget
    if (lane < 6) {
        float contrib = w4c * h3r;
        asm volatile("red.global.add.f32 [%0], %1;"
                     :: "l"(out + lane), "f"(contrib) : "memory");
    }
}

extern "C" void kernel_launch(void* const* d_in, const int* in_sizes, int n_in,
                              void* d_out, int out_size)
{
    const float* x      = (const float*)d_in[0];
    const float* conv_w = (const float*)d_in[1];
    const float* conv_b = (const float*)d_in[2];
    const float* w0     = (const float*)d_in[3];
    const float* b0     = (const float*)d_in[4];
    const float* w1     = (const float*)d_in[5];
    const float* b1     = (const float*)d_in[6];
    const float* w2     = (const float*)d_in[7];
    const float* b2     = (const float*)d_in[8];
    const float* w3     = (const float*)d_in[9];
    const float* b3     = (const float*)d_in[10];
    const float* w4     = (const float*)d_in[11];
    const float* b4     = (const float*)d_in[12];
    float* out = (float*)d_out;

    actor_init<<<1, 32>>>(b4, out);
    actor_main<<<64, 128>>>(x, conv_w, conv_b, w0, b0, w1, b1, w2, b2,
                            w3, b3, w4, out);
}